// round 16
// baseline (speedup 1.0000x reference)
#include <cuda_runtime.h>
#include <cuda_fp16.h>
#include <math.h>
#include <stdint.h>

#define DM 768
#define DI 1536
#define DS 16
#define RK 48
#define XD 80      // RK + 2*DS
#define LQ 1024
#define MROWS 4096 // B*L

typedef __half f16;

// ---------------- scratch ----------------
__device__ __align__(128) float g_xz  [2u * MROWS * 2 * DI];
__device__ __align__(128) f16   g_uh  [4u * MROWS * DI];
__device__ __align__(128) f16   g_ul  [4u * MROWS * DI];
__device__ __align__(128) float g_xdbl[4u * MROWS * XD];
__device__ __align__(128) f16   g_xdblh[4u * MROWS * 64];
__device__ __align__(128) f16   g_xdbll[4u * MROWS * 64];
__device__ __align__(128) float g_dt  [4u * MROWS * DI];
__device__ __align__(128) float g_y   [4u * MROWS * DI];
__device__ __align__(128) f16   g_ych [2u * MROWS * DI];
__device__ __align__(128) f16   g_ycl [2u * MROWS * DI];
__device__ __align__(128) f16   g_hnh [2u * MROWS * DM];
__device__ __align__(128) f16   g_hnl [2u * MROWS * DM];
__device__ __align__(128) f16  g_inwh [2u * 2 * DI * DM];
__device__ __align__(128) f16  g_inwl [2u * 2 * DI * DM];
__device__ __align__(128) f16  g_xpwh [2u * XD * DI];
__device__ __align__(128) f16  g_xpwl [2u * XD * DI];
__device__ __align__(128) f16  g_xpwhb[2u * XD * DI];
__device__ __align__(128) f16  g_xpwlb[2u * XD * DI];
__device__ __align__(128) f16  g_dtwh [2u * DI * 64];
__device__ __align__(128) f16  g_dtwl [2u * DI * 64];
__device__ __align__(128) f16  g_dtwhb[2u * DI * 64];
__device__ __align__(128) f16  g_dtwlb[2u * DI * 64];
__device__ __align__(128) f16  g_outwh[2u * DM * DI];
__device__ __align__(128) f16  g_outwl[2u * DM * DI];

__device__ __forceinline__ float softplus_f(float x)
{
    if (x > 20.f) return x;
    return log1pf(expf(x));
}
__device__ __forceinline__ void split1(float f, f16& h, f16& l)
{
    h = __float2half_rn(f);
    l = __float2half_rn(f - __half2float(h));
}
__device__ __forceinline__ uint32_t packh(f16 a, f16 b)
{
    __half2 p = __halves2half2(a, b);
    return *(uint32_t*)&p;
}

// ---------------- weight splits ----------------
#define S_INW (2 * 2 * DI * DM)
#define S_XPW (2 * XD * DI)
#define S_DTW (2 * DI * 64)
#define S_OUTW (2 * DM * DI)
#define S_REST (2 * S_XPW + 2 * S_DTW + S_OUTW)

__global__ void split_inw(const float* __restrict__ in_w)
{
    int idx = blockIdx.x * 256 + threadIdx.x;
    if (idx >= S_INW) return;
    f16 h, l; split1(in_w[idx], h, l);
    g_inwh[idx] = h; g_inwl[idx] = l;
}

__global__ void split_rest(const float* __restrict__ xp_w, const float* __restrict__ xp_w_b,
                           const float* __restrict__ dtp_w, const float* __restrict__ dtp_w_b,
                           const float* __restrict__ out_w)
{
    int idx = blockIdx.x * 256 + threadIdx.x;
    const float* src; f16 *dh, *dl; int Ks, Kd; int off;
    if ((off = idx) < S_XPW) {
        src = xp_w; dh = g_xpwh; dl = g_xpwl; Ks = DI; Kd = DI;
    } else if ((off = idx - S_XPW) < S_XPW) {
        src = xp_w_b; dh = g_xpwhb; dl = g_xpwlb; Ks = DI; Kd = DI;
    } else if ((off = idx - 2 * S_XPW) < S_DTW) {
        src = dtp_w; dh = g_dtwh; dl = g_dtwl; Ks = RK; Kd = 64;
    } else if ((off = idx - 2 * S_XPW - S_DTW) < S_DTW) {
        src = dtp_w_b; dh = g_dtwhb; dl = g_dtwlb; Ks = RK; Kd = 64;
    } else {
        off = idx - 2 * S_XPW - 2 * S_DTW;
        if (off >= S_OUTW) return;
        src = out_w; dh = g_outwh; dl = g_outwl; Ks = DI; Kd = DI;
    }
    int r = off / Kd, c = off % Kd;
    float v = (c < Ks) ? src[(size_t)r * Ks + c] : 0.f;
    f16 h, l; split1(v, h, l);
    dh[off] = h; dl[off] = l;
}

// ---------------- LayerNorm (float4 vectorized, 192 threads) ----------------
__global__ void ln_kernel(const float* __restrict__ h_r, const float* __restrict__ h_i,
                          const float* __restrict__ ln_w, const float* __restrict__ ln_b)
{
    int row = blockIdx.x;
    int v = row >> 12;
    int m = row & (MROWS - 1);
    const float* src = (v ? h_i : h_r) + (size_t)m * DM;
    int tid = threadIdx.x;
    float4 x = *(const float4*)(src + tid * 4);
    float s = x.x + x.y + x.z + x.w;
    float q = x.x*x.x + x.y*x.y + x.z*x.z + x.w*x.w;
    #pragma unroll
    for (int o = 16; o; o >>= 1) {
        s += __shfl_xor_sync(0xffffffffu, s, o);
        q += __shfl_xor_sync(0xffffffffu, q, o);
    }
    __shared__ float ss[8], qq[8];
    int w = tid >> 5, l = tid & 31;
    if (!l) { ss[w] = s; qq[w] = q; }
    __syncthreads();
    if (tid < 32) {
        s = (tid < 6) ? ss[tid] : 0.f;
        q = (tid < 6) ? qq[tid] : 0.f;
        #pragma unroll
        for (int o = 4; o; o >>= 1) {
            s += __shfl_xor_sync(0xffffffffu, s, o);
            q += __shfl_xor_sync(0xffffffffu, q, o);
        }
        if (!tid) { ss[0] = s; qq[0] = q; }
    }
    __syncthreads();
    float mu = ss[0] * (1.f / DM);
    float var = qq[0] * (1.f / DM) - mu * mu;
    float rstd = rsqrtf(var + 1e-5f);
    size_t base = ((size_t)v * MROWS + m) * DM + tid * 4;
    float4 lw = *(const float4*)(ln_w + v * DM + tid * 4);
    float4 lb = *(const float4*)(ln_b + v * DM + tid * 4);
    float o0 = (x.x - mu) * rstd * lw.x + lb.x;
    float o1 = (x.y - mu) * rstd * lw.y + lb.y;
    float o2 = (x.z - mu) * rstd * lw.z + lb.z;
    float o3 = (x.w - mu) * rstd * lw.w + lb.w;
    f16 h0, l0, h1, l1, h2, l2, h3, l3;
    split1(o0, h0, l0); split1(o1, h1, l1);
    split1(o2, h2, l2); split1(o3, h3, l3);
    *(uint2*)(g_hnh + base) = make_uint2(packh(h0, h1), packh(h2, h3));
    *(uint2*)(g_hnl + base) = make_uint2(packh(l0, l1), packh(l2, l3));
}

// ---------------- fp16 HMMA GEMM-NT: BM=128 BN=64 BK=64, 2 CTAs/SM ----------
// 3-pass split (Ah*Wh + Al*Wh + Ah*Wl) for tiles with n0 < n2p;
// 2-pass (drop Ah*Wl; W rounded to one fp16) for tiles with n0 >= n2p.
#define OAH 0
#define OAL 16384
#define OWH 32768
#define OWL 40960
#define STG  49152
#define GSM  (2 * STG + 1024)

__device__ __forceinline__ void mma_f16(float* d, const uint32_t* a, const uint32_t* b)
{
    asm volatile(
        "mma.sync.aligned.m16n8k16.row.col.f32.f16.f16.f32 "
        "{%0,%1,%2,%3}, {%4,%5,%6,%7}, {%8,%9}, {%0,%1,%2,%3};"
        : "+f"(d[0]), "+f"(d[1]), "+f"(d[2]), "+f"(d[3])
        : "r"(a[0]), "r"(a[1]), "r"(a[2]), "r"(a[3]), "r"(b[0]), "r"(b[1]));
}
#define LDSM4(r0, r1, r2, r3, addr) \
    asm volatile("ldmatrix.sync.aligned.m8n8.x4.shared.b16 {%0,%1,%2,%3}, [%4];" \
                 : "=r"(r0), "=r"(r1), "=r"(r2), "=r"(r3) : "r"(addr))

__global__ __launch_bounds__(256, 2) void gemm_mma2(
    const f16* __restrict__ Ahb, const f16* __restrict__ Alb,
    const f16* __restrict__ Whf, const f16* __restrict__ Wlf,
    const f16* __restrict__ Whb, const f16* __restrict__ Wlb,
    float* __restrict__ Cb, int N, int K, int lda, int ldw, int ldc,
    size_t sA, size_t sW, size_t sC,
    const float* __restrict__ biasf, const float* __restrict__ biasbk, int sBias,
    int epi, int zmode, int n2p)
{
    extern __shared__ __align__(16) char smem[];
    uint32_t sb0;
    asm("{ .reg .u64 t; cvta.to.shared.u64 t, %1; cvt.u32.u64 %0, t; }"
        : "=r"(sb0) : "l"(smem));
    uint32_t sbase = (sb0 + 1023) & ~1023u;

    int z = blockIdx.z;
    int v = zmode ? (z >> 1) : z;
    int dir = zmode ? (z & 1) : 0;
    const f16* Ahp = Ahb + (size_t)z * sA;
    const f16* Alp = Alb + (size_t)z * sA;
    const f16* Whp = (dir ? Whb : Whf) + (size_t)v * sW;
    const f16* Wlp = (dir ? Wlb : Wlf) + (size_t)v * sW;
    const float* bias = dir ? biasbk : biasf;
    float* C = Cb + (size_t)z * sC;

    int tid = threadIdx.x;
    int m0 = blockIdx.y * 128;
    int n0 = blockIdx.x * 64;
    int NT = N - n0; if (NT > 64) NT = 64;
    bool twoPass = (n0 >= n2p);

    int warp = tid >> 5, lane = tid & 31;
    int rowA0 = (warp >> 1) * 32;
    int colB0 = (warp & 1) * 32;
    int g = lane >> 2, tg = lane & 3;

    uint32_t swx  = (uint32_t)(lane & 7) << 4;
    uint32_t lkA  = (uint32_t)(lane >> 4) * 16;
    uint32_t rowbA = (uint32_t)(lane & 15) * 128;
    uint32_t lkB  = (uint32_t)((lane >> 3) & 1) * 16;
    uint32_t rowbB = (uint32_t)((lane & 7) | ((lane & 16) >> 1)) * 128;

    float acc[2][4][4];
    #pragma unroll
    for (int i = 0; i < 2; i++)
        #pragma unroll
        for (int j = 0; j < 4; j++)
            #pragma unroll
            for (int r = 0; r < 4; r++) acc[i][j][r] = 0.f;

    int rl = tid >> 3;
    int c8 = tid & 7;
    uint32_t stcol = ((uint32_t)c8 * 16) ^ (((uint32_t)rl & 7) << 4);
    auto issue_loads = [&](int stage, int k0) {
        uint32_t sb = sbase + (uint32_t)stage * STG;
        #pragma unroll
        for (int i = 0; i < 12; i++) {
            if (i >= 10 && twoPass) continue;   // WL unused in 2-pass tiles
            uint32_t sa; const f16* gp; int sz = 16;
            if (i < 8) {
                int half = i >> 2;
                int r = (i & 3) * 32 + rl;
                sa = sb + (half ? OAL : OAH) + (uint32_t)r * 128 + stcol;
                gp = (half ? Alp : Ahp) + (size_t)(m0 + r) * lda + k0 + c8 * 8;
            } else {
                int r = (i & 1) * 32 + rl;
                sa = sb + (i < 10 ? OWH : OWL) + (uint32_t)r * 128 + stcol;
                int rw = (r < NT) ? r : 0;
                gp = (i < 10 ? Whp : Wlp) + (size_t)(n0 + rw) * ldw + k0 + c8 * 8;
                if (r >= NT) sz = 0;
            }
            asm volatile("cp.async.cg.shared.global [%0], [%1], 16, %2;"
                         :: "r"(sa), "l"(gp), "r"(sz));
        }
        asm volatile("cp.async.commit_group;" ::: "memory");
    };

    int nChunks = K >> 6;
    issue_loads(0, 0);

    for (int ch = 0; ch < nChunks; ch++) {
        __syncthreads();
        if (ch + 1 < nChunks) {
            issue_loads((ch + 1) & 1, (ch + 1) << 6);
            asm volatile("cp.async.wait_group 1;" ::: "memory");
        } else {
            asm volatile("cp.async.wait_group 0;" ::: "memory");
        }
        __syncthreads();

        uint32_t SB = sbase + (uint32_t)(ch & 1) * STG;
        uint32_t uAH = SB + OAH, uAL = SB + OAL, uWH = SB + OWH, uWL = SB + OWL;

        #pragma unroll
        for (int kk = 0; kk < 4; kk++) {
            uint32_t kboff = (uint32_t)kk * 32;
            uint32_t colA = (kboff | lkA) ^ swx;
            uint32_t colB = (kboff | lkB) ^ swx;
            uint32_t aH[2][4], aL[2][4], bH[4][2], bL[4][2];
            #pragma unroll
            for (int mt = 0; mt < 2; mt++) {
                uint32_t ra = (uint32_t)(rowA0 + mt * 16) * 128 + rowbA + colA;
                LDSM4(aH[mt][0], aH[mt][1], aH[mt][2], aH[mt][3], uAH + ra);
                LDSM4(aL[mt][0], aL[mt][1], aL[mt][2], aL[mt][3], uAL + ra);
            }
            #pragma unroll
            for (int ntp = 0; ntp < 2; ntp++) {
                uint32_t rb = (uint32_t)(colB0 + ntp * 16) * 128 + rowbB + colB;
                LDSM4(bH[2*ntp][0], bH[2*ntp][1], bH[2*ntp+1][0], bH[2*ntp+1][1], uWH + rb);
                if (!twoPass)
                    LDSM4(bL[2*ntp][0], bL[2*ntp][1], bL[2*ntp+1][0], bL[2*ntp+1][1], uWL + rb);
            }
            #pragma unroll
            for (int mt = 0; mt < 2; mt++)
                #pragma unroll
                for (int nt = 0; nt < 4; nt++) {
                    mma_f16(acc[mt][nt], aH[mt], bH[nt]);
                    mma_f16(acc[mt][nt], aL[mt], bH[nt]);
                    if (!twoPass)
                        mma_f16(acc[mt][nt], aH[mt], bL[nt]);
                }
        }
    }

    #pragma unroll
    for (int mt = 0; mt < 2; mt++) {
        #pragma unroll
        for (int nt = 0; nt < 4; nt++) {
            int rr = m0 + rowA0 + mt * 16 + g;
            int cn = n0 + colB0 + nt * 8 + tg * 2;
            float e[4] = {acc[mt][nt][0], acc[mt][nt][1], acc[mt][nt][2], acc[mt][nt][3]};
            if (epi == 1) {
                if (cn < N) {
                    float b0 = bias[(size_t)v * sBias + cn];
                    float b1 = bias[(size_t)v * sBias + cn + 1];
                    e[0] = softplus_f(e[0] + b0); e[1] = softplus_f(e[1] + b1);
                    e[2] = softplus_f(e[2] + b0); e[3] = softplus_f(e[3] + b1);
                }
            }
            if (epi == 2) {
                #pragma unroll
                for (int hrow = 0; hrow < 2; hrow++) {
                    int row = rr + hrow * 8;
                    size_t zrow = (size_t)z * MROWS + row;
                    #pragma unroll
                    for (int cc = 0; cc < 2; cc++) {
                        int n = cn + cc;
                        float val = e[hrow * 2 + cc];
                        if (n < XD) C[(size_t)row * ldc + n] = val;
                        if (n < 64) {
                            f16 hh = __float2half_rn(0.f), ll = __float2half_rn(0.f);
                            if (n < RK) split1(val, hh, ll);
                            g_xdblh[zrow * 64 + n] = hh;
                            g_xdbll[zrow * 64 + n] = ll;
                        }
                    }
                }
            } else if (cn < N) {
                *(float2*)(C + (size_t)rr * ldc + cn)       = make_float2(e[0], e[1]);
                *(float2*)(C + (size_t)(rr + 8) * ldc + cn) = make_float2(e[2], e[3]);
            }
        }
    }
}

// ---------------- causal depthwise conv (k=4) + SiLU, x4 vectorized ----------
__global__ void conv_silu_kernel(const float* __restrict__ conv_w, const float* __restrict__ conv_b,
                                 const float* __restrict__ conv_w_b, const float* __restrict__ conv_b_b)
{
    int d4 = (blockIdx.x * 128 + threadIdx.x) * 4;
    int chunk = blockIdx.y;
    int cb = blockIdx.z;
    int c = cb >> 2, b = cb & 3;
    int v = c >> 1, dir = c & 1;

    const float* cwb = (dir ? conv_w_b : conv_w) + ((size_t)v * DI + d4) * 4;
    float4 w0 = *(const float4*)(cwb);
    float4 w1 = *(const float4*)(cwb + 4);
    float4 w2 = *(const float4*)(cwb + 8);
    float4 w3 = *(const float4*)(cwb + 12);
    float4 bias = *(const float4*)((dir ? conv_b_b : conv_b) + v * DI + d4);

    const float* xbase = g_xz + ((size_t)v * MROWS + b * LQ) * (2 * DI) + d4;
    size_t ub = ((size_t)c * MROWS + b * LQ) * DI + d4;

    int s0 = chunk * 64;
    auto fetch = [&](int s) -> float4 {
        if (s < 0) return make_float4(0.f, 0.f, 0.f, 0.f);
        int t = dir ? (LQ - 1 - s) : s;
        return *(const float4*)(xbase + (size_t)t * (2 * DI));
    };
    float4 xm3 = fetch(s0 - 3), xm2 = fetch(s0 - 2), xm1 = fetch(s0 - 1);
    #pragma unroll 4
    for (int s = s0; s < s0 + 64; s++) {
        float4 xc = fetch(s);
        float o0 = fmaf(xm3.x, w0.x, fmaf(xm2.x, w0.y, fmaf(xm1.x, w0.z, fmaf(xc.x, w0.w, bias.x))));
        float o1 = fmaf(xm3.y, w1.x, fmaf(xm2.y, w1.y, fmaf(xm1.y, w1.z, fmaf(xc.y, w1.w, bias.y))));
        float o2 = fmaf(xm3.z, w2.x, fmaf(xm2.z, w2.y, fmaf(xm1.z, w2.z, fmaf(xc.z, w2.w, bias.z))));
        float o3 = fmaf(xm3.w, w3.x, fmaf(xm2.w, w3.y, fmaf(xm1.w, w3.z, fmaf(xc.w, w3.w, bias.w))));
        o0 = o0 * (1.f / (1.f + __expf(-o0)));
        o1 = o1 * (1.f / (1.f + __expf(-o1)));
        o2 = o2 * (1.f / (1.f + __expf(-o2)));
        o3 = o3 * (1.f / (1.f + __expf(-o3)));
        f16 h0, l0, h1, l1, h2, l2, h3, l3;
        split1(o0, h0, l0); split1(o1, h1, l1);
        split1(o2, h2, l2); split1(o3, h3, l3);
        size_t idx = ub + (size_t)s * DI;
        *(uint2*)(g_uh + idx) = make_uint2(packh(h0, h1), packh(h2, h3));
        *(uint2*)(g_ul + idx) = make_uint2(packh(l0, l1), packh(l2, l3));
        xm3 = xm2; xm2 = xm1; xm1 = xc;
    }
}

// ---------------- selective scan (16-step register prefetch, 192x128) --------
__global__ __launch_bounds__(128) void scan_kernel(const float* __restrict__ A_log,
                                                   const float* __restrict__ A_b_log,
                                                   const float* __restrict__ D_p,
                                                   const float* __restrict__ D_b)
{
    int bi = blockIdx.x;
    int cb = bi / 12, dgblk = bi % 12;
    int c = cb >> 2, b = cb & 3;
    int warp = threadIdx.x >> 5, lane = threadIdx.x & 31;
    int dg = dgblk * 4 + warp;
    int d = dg * 32 + lane;
    int v = c >> 1, dir = c & 1;

    const float L2E = 1.44269504088896340736f;
    const float* al = (dir ? A_b_log : A_log) + ((size_t)v * DI + d) * DS;
    float A2[16];
    bool okl = true;
    #pragma unroll
    for (int n = 0; n < 16; n++) {
        A2[n] = -expf(al[n]) * L2E;
        float want = -(float)(n + 1) * L2E;
        okl &= fabsf(A2[n] - want) <= 1e-3f * (float)(n + 1) * L2E;
    }
    bool fast = __all_sync(0xffffffffu, okl);
    float Dd = (dir ? D_b : D_p)[v * DI + d];

    float h[16];
    #pragma unroll
    for (int n = 0; n < 16; n++) h[n] = 0.f;

    size_t rbase = ((size_t)c * 4 + b) * LQ;
    const float* xdb = g_xdbl + rbase * XD + 48 + lane;
    const float* dtp = g_dt   + rbase * DI + d;
    const f16*   uhp = g_uh   + rbase * DI + d;
    const f16*   ulp = g_ul   + rbase * DI + d;
    float* yp        = g_y    + rbase * DI + d;

    __shared__ __align__(16) float sBC[16][32];

    if (fast) {
        for (int chunk = 0; chunk < LQ / 16; chunk++) {
            __syncthreads();
            #pragma unroll
            for (int i = 0; i < 4; i++) {
                int sl = warp + i * 4;
                sBC[sl][lane] = xdb[(size_t)(chunk * 16 + sl) * XD];
            }
            float dtv[16], uhv[16], ulv[16];
            #pragma unroll
            for (int i = 0; i < 16; i++)
                dtv[i] = dtp[(size_t)(chunk * 16 + i) * DI];
            #pragma unroll
            for (int i = 0; i < 16; i++) {
                uhv[i] = __half2float(uhp[(size_t)(chunk * 16 + i) * DI]);
                ulv[i] = __half2float(ulp[(size_t)(chunk * 16 + i) * DI]);
            }
            __syncthreads();
            #pragma unroll
            for (int s16 = 0; s16 < 16; s16++) {
                int s = chunk * 16 + s16;
                float dt = dtv[s16];
                float u  = uhv[s16] + ulv[s16];
                float dtu = dt * u;
                float y0 = u * Dd, y1 = 0.f;
                float r;
                asm("ex2.approx.ftz.f32 %0, %1;" : "=f"(r) : "f"(dt * A2[0]));
                float rp[17];
                rp[1] = r;
                #pragma unroll
                for (int n = 2; n <= 16; n++) rp[n] = rp[n >> 1] * rp[n - (n >> 1)];
                #pragma unroll
                for (int n = 0; n < 16; n += 2) {
                    float b0 = sBC[s16][n],     c0 = sBC[s16][16 + n];
                    float b1 = sBC[s16][n + 1], c1 = sBC[s16][16 + n + 1];
                    h[n]     = fmaf(rp[n + 1], h[n],     dtu * b0);
                    h[n + 1] = fmaf(rp[n + 2], h[n + 1], dtu * b1);
                    y0 = fmaf(h[n],     c0, y0);
                    y1 = fmaf(h[n + 1], c1, y1);
                }
                yp[(size_t)s * DI] = y0 + y1;
            }
        }
    } else {
        for (int chunk = 0; chunk < LQ / 16; chunk++) {
            __syncthreads();
            #pragma unroll
            for (int i = 0; i < 4; i++) {
                int sl = warp + i * 4;
                sBC[sl][lane] = xdb[(size_t)(chunk * 16 + sl) * XD];
            }
            float dtv[16], uhv[16], ulv[16];
            #pragma unroll
            for (int i = 0; i < 16; i++)
                dtv[i] = dtp[(size_t)(chunk * 16 + i) * DI];
            #pragma unroll
            for (int i = 0; i < 16; i++) {
                uhv[i] = __half2float(uhp[(size_t)(chunk * 16 + i) * DI]);
                ulv[i] = __half2float(ulp[(size_t)(chunk * 16 + i) * DI]);
            }
            __syncthreads();
            #pragma unroll
            for (int s16 = 0; s16 < 16; s16++) {
                int s = chunk * 16 + s16;
                float dt = dtv[s16];
                float u  = uhv[s16] + ulv[s16];
                float dtu = dt * u;
                float y0 = u * Dd, y1 = 0.f;
                #pragma unroll
                for (int n = 0; n < 16; n += 2) {
                    float dA0, dA1;
                    asm("ex2.approx.ftz.f32 %0, %1;" : "=f"(dA0) : "f"(dt * A2[n]));
                    asm("ex2.approx.ftz.f32 %0, %1;" : "=f"(dA1) : "f"(dt * A2[n + 1]));
                    h[n]     = fmaf(dA0, h[n],     dtu * sBC[s16][n]);
                    h[n + 1] = fmaf(dA1, h[n + 1], dtu * sBC[s16][n + 1]);
                    y0 = fmaf(h[n],     sBC[s16][16 + n],     y0);
                    y1 = fmaf(h[n + 1], sBC[s16][16 + n + 1], y1);
                }
                yp[(size_t)s * DI] = y0 + y1;
            }
        }
    }
}

// ---------------- combine + gate, x4 vectorized ----------------
__global__ void combine_kernel()
{
    size_t idx4 = ((size_t)blockIdx.x * 256 + threadIdx.x) * 4;
    int d = (int)(idx4 % DI);
    size_t rm = idx4 / DI;
    int t = (int)(rm & (LQ - 1));
    int b = (int)((rm >> 10) & 3);
    int v = (int)(rm >> 12);
    float4 yf = *(const float4*)&g_y[(((size_t)(2 * v)     * 4 + b) * LQ + t)            * DI + d];
    float4 yb = *(const float4*)&g_y[(((size_t)(2 * v + 1) * 4 + b) * LQ + (LQ - 1 - t)) * DI + d];
    float4 z  = *(const float4*)&g_xz[((size_t)v * MROWS + b * LQ + t) * (2 * DI) + DI + d];
    float v0 = (yf.x + yb.x) * (z.x / (1.f + __expf(-z.x)));
    float v1 = (yf.y + yb.y) * (z.y / (1.f + __expf(-z.y)));
    float v2 = (yf.z + yb.z) * (z.z / (1.f + __expf(-z.z)));
    float v3 = (yf.w + yb.w) * (z.w / (1.f + __expf(-z.w)));
    f16 h0, l0, h1, l1, h2, l2, h3, l3;
    split1(v0, h0, l0); split1(v1, h1, l1);
    split1(v2, h2, l2); split1(v3, h3, l3);
    *(uint2*)(g_ych + idx4) = make_uint2(packh(h0, h1), packh(h2, h3));
    *(uint2*)(g_ycl + idx4) = make_uint2(packh(l0, l1), packh(l2, l3));
}

// ---------------- launch ----------------
extern "C" void kernel_launch(void* const* d_in, const int* in_sizes, int n_in,
                              void* d_out, int out_size)
{
    const float* h_r        = (const float*)d_in[0];
    const float* h_i        = (const float*)d_in[1];
    const float* ln_w       = (const float*)d_in[2];
    const float* ln_b       = (const float*)d_in[3];
    const float* in_w       = (const float*)d_in[4];
    const float* conv_w     = (const float*)d_in[5];
    const float* conv_bias  = (const float*)d_in[6];
    const float* xp_w       = (const float*)d_in[7];
    const float* dtp_w      = (const float*)d_in[8];
    const float* dtp_bias   = (const float*)d_in[9];
    const float* A_log      = (const float*)d_in[10];
    const float* D_p        = (const float*)d_in[11];
    const float* conv_w_b   = (const float*)d_in[12];
    const float* conv_bias_b= (const float*)d_in[13];
    const float* xp_w_b     = (const float*)d_in[14];
    const float* dtp_w_b    = (const float*)d_in[15];
    const float* dtp_bias_b = (const float*)d_in[16];
    const float* A_b_log    = (const float*)d_in[17];
    const float* D_b        = (const float*)d_in[18];
    const float* out_w      = (const float*)d_in[19];
    float* out = (float*)d_out;

    f16 *p_hnh, *p_hnl, *p_uh, *p_ul, *p_xdh, *p_xdl, *p_ych, *p_ycl;
    f16 *p_inwh, *p_inwl, *p_xpwh, *p_xpwl, *p_xpwhb, *p_xpwlb;
    f16 *p_dtwh, *p_dtwl, *p_dtwhb, *p_dtwlb, *p_outwh, *p_outwl;
    float *p_xz, *p_xdbl, *p_dt;
    cudaGetSymbolAddress((void**)&p_hnh, g_hnh);   cudaGetSymbolAddress((void**)&p_hnl, g_hnl);
    cudaGetSymbolAddress((void**)&p_uh,  g_uh);    cudaGetSymbolAddress((void**)&p_ul,  g_ul);
    cudaGetSymbolAddress((void**)&p_xdh, g_xdblh); cudaGetSymbolAddress((void**)&p_xdl, g_xdbll);
    cudaGetSymbolAddress((void**)&p_ych, g_ych);   cudaGetSymbolAddress((void**)&p_ycl, g_ycl);
    cudaGetSymbolAddress((void**)&p_inwh, g_inwh); cudaGetSymbolAddress((void**)&p_inwl, g_inwl);
    cudaGetSymbolAddress((void**)&p_xpwh, g_xpwh); cudaGetSymbolAddress((void**)&p_xpwl, g_xpwl);
    cudaGetSymbolAddress((void**)&p_xpwhb, g_xpwhb); cudaGetSymbolAddress((void**)&p_xpwlb, g_xpwlb);
    cudaGetSymbolAddress((void**)&p_dtwh, g_dtwh); cudaGetSymbolAddress((void**)&p_dtwl, g_dtwl);
    cudaGetSymbolAddress((void**)&p_dtwhb, g_dtwhb); cudaGetSymbolAddress((void**)&p_dtwlb, g_dtwlb);
    cudaGetSymbolAddress((void**)&p_outwh, g_outwh); cudaGetSymbolAddress((void**)&p_outwl, g_outwl);
    cudaGetSymbolAddress((void**)&p_xz, g_xz);
    cudaGetSymbolAddress((void**)&p_xdbl, g_xdbl);
    cudaGetSymbolAddress((void**)&p_dt, g_dt);

    static int s_attr = 0;
    if (!s_attr) {
        cudaFuncSetAttribute(gemm_mma2, cudaFuncAttributeMaxDynamicSharedMemorySize, GSM);
        s_attr = 1;
    }

    // idx 0: in_proj weight split
    split_inw<<<(S_INW + 255) / 256, 256>>>(in_w);

    // idx 1: LayerNorm
    ln_kernel<<<2 * MROWS, 192>>>(h_r, h_i, ln_w, ln_b);

    // idx 2: remaining weight splits
    split_rest<<<(S_REST + 255) / 256, 256>>>(xp_w, xp_w_b, dtp_w, dtp_w_b, out_w);

    // idx 3 (profiled): in_proj  (M=4096, N=3072, K=768); z half (n>=1536) 2-pass
    gemm_mma2<<<dim3(48, 32, 2), 256, GSM>>>(
        p_hnh, p_hnl, p_inwh, p_inwl, nullptr, nullptr,
        p_xz, 3072, 768, 768, 768, 3072,
        (size_t)MROWS * DM, (size_t)3072 * DM, (size_t)MROWS * 3072,
        nullptr, nullptr, 0, 0, 0, DI);

    // idx 4: conv + silu -> uh/ul
    conv_silu_kernel<<<dim3(3, 16, 16), 128>>>(conv_w, conv_bias, conv_w_b, conv_bias_b);

    // idx 5: xp projection (N=80, K=1536); full 3-pass (feeds dt/B/C)
    gemm_mma2<<<dim3(2, 32, 4), 256, GSM>>>(
        p_uh, p_ul, p_xpwh, p_xpwl, p_xpwhb, p_xpwlb,
        p_xdbl, XD, DI, DI, DI, XD,
        (size_t)MROWS * DI, (size_t)XD * DI, (size_t)MROWS * XD,
        nullptr, nullptr, 0, 2, 1, 1 << 30);

    // idx 6: dt projection + softplus (N=1536, K=64 padded); full 3-pass
    gemm_mma2<<<dim3(24, 32, 4), 256, GSM>>>(
        p_xdh, p_xdl, p_dtwh, p_dtwl, p_dtwhb, p_dtwlb,
        p_dt, DI, 64, 64, 64, DI,
        (size_t)MROWS * 64, (size_t)DI * 64, (size_t)MROWS * DI,
        dtp_bias, dtp_bias_b, DI, 1, 1, 1 << 30);

    // idx 7: selective scan
    scan_kernel<<<192, 128>>>(A_log, A_b_log, D_p, D_b);

    // idx 8: combine + gate
    combine_kernel<<<(2 * MROWS * DI) / 1024, 256>>>();

    // idx 9: out_proj (M=4096, N=768, K=1536); 2-pass everywhere (final op)
    gemm_mma2<<<dim3(12, 32, 2), 256, GSM>>>(
        p_ych, p_ycl, p_outwh, p_outwl, nullptr, nullptr,
        out, DM, DI, DI, DI, DM,
        (size_t)MROWS * DI, (size_t)DM * DI, (size_t)MROWS * DM,
        nullptr, nullptr, 0, 0, 0, 0);
}

// round 17
// speedup vs baseline: 1.0943x; 1.0943x over previous
#include <cuda_runtime.h>
#include <cuda_fp16.h>
#include <math.h>
#include <stdint.h>

#define DM 768
#define DI 1536
#define DS 16
#define RK 48
#define XD 80      // RK + 2*DS
#define LQ 1024
#define MROWS 4096 // B*L

typedef __half f16;

// ---------------- scratch ----------------
__device__ __align__(128) float g_xz  [2u * MROWS * 2 * DI];
__device__ __align__(128) f16   g_uh  [4u * MROWS * DI];
__device__ __align__(128) f16   g_ul  [4u * MROWS * DI];
__device__ __align__(128) float g_xdbl[4u * MROWS * XD];
__device__ __align__(128) f16   g_xdblh[4u * MROWS * 64];
__device__ __align__(128) f16   g_xdbll[4u * MROWS * 64];
__device__ __align__(128) float g_dt  [4u * MROWS * DI];
__device__ __align__(128) float g_y   [4u * MROWS * DI];
__device__ __align__(128) f16   g_ych [2u * MROWS * DI];
__device__ __align__(128) f16   g_ycl [2u * MROWS * DI];
__device__ __align__(128) f16   g_hnh [2u * MROWS * DM];
__device__ __align__(128) f16   g_hnl [2u * MROWS * DM];
__device__ __align__(128) f16  g_inwh [2u * 2 * DI * DM];
__device__ __align__(128) f16  g_inwl [2u * 2 * DI * DM];
__device__ __align__(128) f16  g_xpwh [2u * XD * DI];
__device__ __align__(128) f16  g_xpwl [2u * XD * DI];
__device__ __align__(128) f16  g_xpwhb[2u * XD * DI];
__device__ __align__(128) f16  g_xpwlb[2u * XD * DI];
__device__ __align__(128) f16  g_dtwh [2u * DI * 64];
__device__ __align__(128) f16  g_dtwl [2u * DI * 64];
__device__ __align__(128) f16  g_dtwhb[2u * DI * 64];
__device__ __align__(128) f16  g_dtwlb[2u * DI * 64];
__device__ __align__(128) f16  g_outwh[2u * DM * DI];
__device__ __align__(128) f16  g_outwl[2u * DM * DI];

__device__ __forceinline__ float softplus_f(float x)
{
    if (x > 20.f) return x;
    return log1pf(expf(x));
}
__device__ __forceinline__ void split1(float f, f16& h, f16& l)
{
    h = __float2half_rn(f);
    l = __float2half_rn(f - __half2float(h));
}
__device__ __forceinline__ uint32_t packh(f16 a, f16 b)
{
    __half2 p = __halves2half2(a, b);
    return *(uint32_t*)&p;
}

// ---------------- weight splits ----------------
#define S_INW (2 * 2 * DI * DM)
#define S_XPW (2 * XD * DI)
#define S_DTW (2 * DI * 64)
#define S_OUTW (2 * DM * DI)
#define S_REST (2 * S_XPW + 2 * S_DTW + S_OUTW)

__global__ void split_inw(const float* __restrict__ in_w)
{
    int idx = blockIdx.x * 256 + threadIdx.x;
    if (idx >= S_INW) return;
    f16 h, l; split1(in_w[idx], h, l);
    g_inwh[idx] = h; g_inwl[idx] = l;
}

__global__ void split_rest(const float* __restrict__ xp_w, const float* __restrict__ xp_w_b,
                           const float* __restrict__ dtp_w, const float* __restrict__ dtp_w_b,
                           const float* __restrict__ out_w)
{
    int idx = blockIdx.x * 256 + threadIdx.x;
    const float* src; f16 *dh, *dl; int Ks, Kd; int off;
    if ((off = idx) < S_XPW) {
        src = xp_w; dh = g_xpwh; dl = g_xpwl; Ks = DI; Kd = DI;
    } else if ((off = idx - S_XPW) < S_XPW) {
        src = xp_w_b; dh = g_xpwhb; dl = g_xpwlb; Ks = DI; Kd = DI;
    } else if ((off = idx - 2 * S_XPW) < S_DTW) {
        src = dtp_w; dh = g_dtwh; dl = g_dtwl; Ks = RK; Kd = 64;
    } else if ((off = idx - 2 * S_XPW - S_DTW) < S_DTW) {
        src = dtp_w_b; dh = g_dtwhb; dl = g_dtwlb; Ks = RK; Kd = 64;
    } else {
        off = idx - 2 * S_XPW - 2 * S_DTW;
        if (off >= S_OUTW) return;
        src = out_w; dh = g_outwh; dl = g_outwl; Ks = DI; Kd = DI;
    }
    int r = off / Kd, c = off % Kd;
    float v = (c < Ks) ? src[(size_t)r * Ks + c] : 0.f;
    f16 h, l; split1(v, h, l);
    dh[off] = h; dl[off] = l;
}

// ---------------- LayerNorm (float4 vectorized, 192 threads) ----------------
__global__ void ln_kernel(const float* __restrict__ h_r, const float* __restrict__ h_i,
                          const float* __restrict__ ln_w, const float* __restrict__ ln_b)
{
    int row = blockIdx.x;
    int v = row >> 12;
    int m = row & (MROWS - 1);
    const float* src = (v ? h_i : h_r) + (size_t)m * DM;
    int tid = threadIdx.x;
    float4 x = *(const float4*)(src + tid * 4);
    float s = x.x + x.y + x.z + x.w;
    float q = x.x*x.x + x.y*x.y + x.z*x.z + x.w*x.w;
    #pragma unroll
    for (int o = 16; o; o >>= 1) {
        s += __shfl_xor_sync(0xffffffffu, s, o);
        q += __shfl_xor_sync(0xffffffffu, q, o);
    }
    __shared__ float ss[8], qq[8];
    int w = tid >> 5, l = tid & 31;
    if (!l) { ss[w] = s; qq[w] = q; }
    __syncthreads();
    if (tid < 32) {
        s = (tid < 6) ? ss[tid] : 0.f;
        q = (tid < 6) ? qq[tid] : 0.f;
        #pragma unroll
        for (int o = 4; o; o >>= 1) {
            s += __shfl_xor_sync(0xffffffffu, s, o);
            q += __shfl_xor_sync(0xffffffffu, q, o);
        }
        if (!tid) { ss[0] = s; qq[0] = q; }
    }
    __syncthreads();
    float mu = ss[0] * (1.f / DM);
    float var = qq[0] * (1.f / DM) - mu * mu;
    float rstd = rsqrtf(var + 1e-5f);
    size_t base = ((size_t)v * MROWS + m) * DM + tid * 4;
    float4 lw = *(const float4*)(ln_w + v * DM + tid * 4);
    float4 lb = *(const float4*)(ln_b + v * DM + tid * 4);
    float o0 = (x.x - mu) * rstd * lw.x + lb.x;
    float o1 = (x.y - mu) * rstd * lw.y + lb.y;
    float o2 = (x.z - mu) * rstd * lw.z + lb.z;
    float o3 = (x.w - mu) * rstd * lw.w + lb.w;
    f16 h0, l0, h1, l1, h2, l2, h3, l3;
    split1(o0, h0, l0); split1(o1, h1, l1);
    split1(o2, h2, l2); split1(o3, h3, l3);
    *(uint2*)(g_hnh + base) = make_uint2(packh(h0, h1), packh(h2, h3));
    *(uint2*)(g_hnl + base) = make_uint2(packh(l0, l1), packh(l2, l3));
}

// ---------------- fp16 HMMA GEMM-NT: BM=128 BN=64 BK=64, 2 CTAs/SM ----------
// TWO=false: 3-pass split (Ah*Wh + Al*Wh + Ah*Wl).
// TWO=true : 2-pass (drop Ah*Wl) — statically branch-free.
#define OAH 0
#define OAL 16384
#define OWH 32768
#define OWL 40960
#define STG  49152
#define GSM  (2 * STG + 1024)

__device__ __forceinline__ void mma_f16(float* d, const uint32_t* a, const uint32_t* b)
{
    asm volatile(
        "mma.sync.aligned.m16n8k16.row.col.f32.f16.f16.f32 "
        "{%0,%1,%2,%3}, {%4,%5,%6,%7}, {%8,%9}, {%0,%1,%2,%3};"
        : "+f"(d[0]), "+f"(d[1]), "+f"(d[2]), "+f"(d[3])
        : "r"(a[0]), "r"(a[1]), "r"(a[2]), "r"(a[3]), "r"(b[0]), "r"(b[1]));
}
#define LDSM4(r0, r1, r2, r3, addr) \
    asm volatile("ldmatrix.sync.aligned.m8n8.x4.shared.b16 {%0,%1,%2,%3}, [%4];" \
                 : "=r"(r0), "=r"(r1), "=r"(r2), "=r"(r3) : "r"(addr))

template<bool TWO>
__global__ __launch_bounds__(256, 2) void gemm_mma2(
    const f16* __restrict__ Ahb, const f16* __restrict__ Alb,
    const f16* __restrict__ Whf, const f16* __restrict__ Wlf,
    const f16* __restrict__ Whb, const f16* __restrict__ Wlb,
    float* __restrict__ Cb, int N, int K, int lda, int ldw, int ldc,
    size_t sA, size_t sW, size_t sC,
    const float* __restrict__ biasf, const float* __restrict__ biasbk, int sBias,
    int epi, int zmode)
{
    extern __shared__ __align__(16) char smem[];
    uint32_t sb0;
    asm("{ .reg .u64 t; cvta.to.shared.u64 t, %1; cvt.u32.u64 %0, t; }"
        : "=r"(sb0) : "l"(smem));
    uint32_t sbase = (sb0 + 1023) & ~1023u;

    int z = blockIdx.z;
    int v = zmode ? (z >> 1) : z;
    int dir = zmode ? (z & 1) : 0;
    const f16* Ahp = Ahb + (size_t)z * sA;
    const f16* Alp = Alb + (size_t)z * sA;
    const f16* Whp = (dir ? Whb : Whf) + (size_t)v * sW;
    const f16* Wlp = TWO ? Whp : ((dir ? Wlb : Wlf) + (size_t)v * sW);
    const float* bias = dir ? biasbk : biasf;
    float* C = Cb + (size_t)z * sC;

    int tid = threadIdx.x;
    int m0 = blockIdx.y * 128;
    int n0 = blockIdx.x * 64;
    int NT = N - n0; if (NT > 64) NT = 64;

    int warp = tid >> 5, lane = tid & 31;
    int rowA0 = (warp >> 1) * 32;
    int colB0 = (warp & 1) * 32;
    int g = lane >> 2, tg = lane & 3;

    uint32_t swx  = (uint32_t)(lane & 7) << 4;
    uint32_t lkA  = (uint32_t)(lane >> 4) * 16;
    uint32_t rowbA = (uint32_t)(lane & 15) * 128;
    uint32_t lkB  = (uint32_t)((lane >> 3) & 1) * 16;
    uint32_t rowbB = (uint32_t)((lane & 7) | ((lane & 16) >> 1)) * 128;

    float acc[2][4][4];
    #pragma unroll
    for (int i = 0; i < 2; i++)
        #pragma unroll
        for (int j = 0; j < 4; j++)
            #pragma unroll
            for (int r = 0; r < 4; r++) acc[i][j][r] = 0.f;

    int rl = tid >> 3;
    int c8 = tid & 7;
    uint32_t stcol = ((uint32_t)c8 * 16) ^ (((uint32_t)rl & 7) << 4);
    const int NLD = TWO ? 10 : 12;
    auto issue_loads = [&](int stage, int k0) {
        uint32_t sb = sbase + (uint32_t)stage * STG;
        #pragma unroll
        for (int i = 0; i < NLD; i++) {
            uint32_t sa; const f16* gp; int sz = 16;
            if (i < 8) {
                int half = i >> 2;
                int r = (i & 3) * 32 + rl;
                sa = sb + (half ? OAL : OAH) + (uint32_t)r * 128 + stcol;
                gp = (half ? Alp : Ahp) + (size_t)(m0 + r) * lda + k0 + c8 * 8;
            } else {
                int r = (i & 1) * 32 + rl;
                sa = sb + (i < 10 ? OWH : OWL) + (uint32_t)r * 128 + stcol;
                int rw = (r < NT) ? r : 0;
                gp = (i < 10 ? Whp : Wlp) + (size_t)(n0 + rw) * ldw + k0 + c8 * 8;
                if (r >= NT) sz = 0;
            }
            asm volatile("cp.async.cg.shared.global [%0], [%1], 16, %2;"
                         :: "r"(sa), "l"(gp), "r"(sz));
        }
        asm volatile("cp.async.commit_group;" ::: "memory");
    };

    int nChunks = K >> 6;
    issue_loads(0, 0);

    for (int ch = 0; ch < nChunks; ch++) {
        __syncthreads();
        if (ch + 1 < nChunks) {
            issue_loads((ch + 1) & 1, (ch + 1) << 6);
            asm volatile("cp.async.wait_group 1;" ::: "memory");
        } else {
            asm volatile("cp.async.wait_group 0;" ::: "memory");
        }
        __syncthreads();

        uint32_t SB = sbase + (uint32_t)(ch & 1) * STG;
        uint32_t uAH = SB + OAH, uAL = SB + OAL, uWH = SB + OWH, uWL = SB + OWL;

        #pragma unroll
        for (int kk = 0; kk < 4; kk++) {
            uint32_t kboff = (uint32_t)kk * 32;
            uint32_t colA = (kboff | lkA) ^ swx;
            uint32_t colB = (kboff | lkB) ^ swx;
            uint32_t aH[2][4], aL[2][4], bH[4][2], bL[4][2];
            #pragma unroll
            for (int mt = 0; mt < 2; mt++) {
                uint32_t ra = (uint32_t)(rowA0 + mt * 16) * 128 + rowbA + colA;
                LDSM4(aH[mt][0], aH[mt][1], aH[mt][2], aH[mt][3], uAH + ra);
                LDSM4(aL[mt][0], aL[mt][1], aL[mt][2], aL[mt][3], uAL + ra);
            }
            #pragma unroll
            for (int ntp = 0; ntp < 2; ntp++) {
                uint32_t rb = (uint32_t)(colB0 + ntp * 16) * 128 + rowbB + colB;
                LDSM4(bH[2*ntp][0], bH[2*ntp][1], bH[2*ntp+1][0], bH[2*ntp+1][1], uWH + rb);
                if (!TWO)
                    LDSM4(bL[2*ntp][0], bL[2*ntp][1], bL[2*ntp+1][0], bL[2*ntp+1][1], uWL + rb);
            }
            #pragma unroll
            for (int mt = 0; mt < 2; mt++)
                #pragma unroll
                for (int nt = 0; nt < 4; nt++) {
                    mma_f16(acc[mt][nt], aH[mt], bH[nt]);
                    mma_f16(acc[mt][nt], aL[mt], bH[nt]);
                    if (!TWO)
                        mma_f16(acc[mt][nt], aH[mt], bL[nt]);
                }
        }
    }

    #pragma unroll
    for (int mt = 0; mt < 2; mt++) {
        #pragma unroll
        for (int nt = 0; nt < 4; nt++) {
            int rr = m0 + rowA0 + mt * 16 + g;
            int cn = n0 + colB0 + nt * 8 + tg * 2;
            float e[4] = {acc[mt][nt][0], acc[mt][nt][1], acc[mt][nt][2], acc[mt][nt][3]};
            if (epi == 1) {
                if (cn < N) {
                    float b0 = bias[(size_t)v * sBias + cn];
                    float b1 = bias[(size_t)v * sBias + cn + 1];
                    e[0] = softplus_f(e[0] + b0); e[1] = softplus_f(e[1] + b1);
                    e[2] = softplus_f(e[2] + b0); e[3] = softplus_f(e[3] + b1);
                }
            }
            if (epi == 2) {
                #pragma unroll
                for (int hrow = 0; hrow < 2; hrow++) {
                    int row = rr + hrow * 8;
                    size_t zrow = (size_t)z * MROWS + row;
                    #pragma unroll
                    for (int cc = 0; cc < 2; cc++) {
                        int n = cn + cc;
                        float val = e[hrow * 2 + cc];
                        if (n < XD) C[(size_t)row * ldc + n] = val;
                        if (n < 64) {
                            f16 hh = __float2half_rn(0.f), ll = __float2half_rn(0.f);
                            if (n < RK) split1(val, hh, ll);
                            g_xdblh[zrow * 64 + n] = hh;
                            g_xdbll[zrow * 64 + n] = ll;
                        }
                    }
                }
            } else if (cn < N) {
                *(float2*)(C + (size_t)rr * ldc + cn)       = make_float2(e[0], e[1]);
                *(float2*)(C + (size_t)(rr + 8) * ldc + cn) = make_float2(e[2], e[3]);
            }
        }
    }
}

// ---------------- causal depthwise conv (k=4) + SiLU, x4 vectorized ----------
__global__ void conv_silu_kernel(const float* __restrict__ conv_w, const float* __restrict__ conv_b,
                                 const float* __restrict__ conv_w_b, const float* __restrict__ conv_b_b)
{
    int d4 = (blockIdx.x * 128 + threadIdx.x) * 4;
    int chunk = blockIdx.y;
    int cb = blockIdx.z;
    int c = cb >> 2, b = cb & 3;
    int v = c >> 1, dir = c & 1;

    const float* cwb = (dir ? conv_w_b : conv_w) + ((size_t)v * DI + d4) * 4;
    float4 w0 = *(const float4*)(cwb);
    float4 w1 = *(const float4*)(cwb + 4);
    float4 w2 = *(const float4*)(cwb + 8);
    float4 w3 = *(const float4*)(cwb + 12);
    float4 bias = *(const float4*)((dir ? conv_b_b : conv_b) + v * DI + d4);

    const float* xbase = g_xz + ((size_t)v * MROWS + b * LQ) * (2 * DI) + d4;
    size_t ub = ((size_t)c * MROWS + b * LQ) * DI + d4;

    int s0 = chunk * 64;
    auto fetch = [&](int s) -> float4 {
        if (s < 0) return make_float4(0.f, 0.f, 0.f, 0.f);
        int t = dir ? (LQ - 1 - s) : s;
        return *(const float4*)(xbase + (size_t)t * (2 * DI));
    };
    float4 xm3 = fetch(s0 - 3), xm2 = fetch(s0 - 2), xm1 = fetch(s0 - 1);
    #pragma unroll 4
    for (int s = s0; s < s0 + 64; s++) {
        float4 xc = fetch(s);
        float o0 = fmaf(xm3.x, w0.x, fmaf(xm2.x, w0.y, fmaf(xm1.x, w0.z, fmaf(xc.x, w0.w, bias.x))));
        float o1 = fmaf(xm3.y, w1.x, fmaf(xm2.y, w1.y, fmaf(xm1.y, w1.z, fmaf(xc.y, w1.w, bias.y))));
        float o2 = fmaf(xm3.z, w2.x, fmaf(xm2.z, w2.y, fmaf(xm1.z, w2.z, fmaf(xc.z, w2.w, bias.z))));
        float o3 = fmaf(xm3.w, w3.x, fmaf(xm2.w, w3.y, fmaf(xm1.w, w3.z, fmaf(xc.w, w3.w, bias.w))));
        o0 = o0 * (1.f / (1.f + __expf(-o0)));
        o1 = o1 * (1.f / (1.f + __expf(-o1)));
        o2 = o2 * (1.f / (1.f + __expf(-o2)));
        o3 = o3 * (1.f / (1.f + __expf(-o3)));
        f16 h0, l0, h1, l1, h2, l2, h3, l3;
        split1(o0, h0, l0); split1(o1, h1, l1);
        split1(o2, h2, l2); split1(o3, h3, l3);
        size_t idx = ub + (size_t)s * DI;
        *(uint2*)(g_uh + idx) = make_uint2(packh(h0, h1), packh(h2, h3));
        *(uint2*)(g_ul + idx) = make_uint2(packh(l0, l1), packh(l2, l3));
        xm3 = xm2; xm2 = xm1; xm1 = xc;
    }
}

// ---------------- selective scan (16-step register prefetch, 192x128) --------
__global__ __launch_bounds__(128) void scan_kernel(const float* __restrict__ A_log,
                                                   const float* __restrict__ A_b_log,
                                                   const float* __restrict__ D_p,
                                                   const float* __restrict__ D_b)
{
    int bi = blockIdx.x;
    int cb = bi / 12, dgblk = bi % 12;
    int c = cb >> 2, b = cb & 3;
    int warp = threadIdx.x >> 5, lane = threadIdx.x & 31;
    int dg = dgblk * 4 + warp;
    int d = dg * 32 + lane;
    int v = c >> 1, dir = c & 1;

    const float L2E = 1.44269504088896340736f;
    const float* al = (dir ? A_b_log : A_log) + ((size_t)v * DI + d) * DS;
    float A2[16];
    bool okl = true;
    #pragma unroll
    for (int n = 0; n < 16; n++) {
        A2[n] = -expf(al[n]) * L2E;
        float want = -(float)(n + 1) * L2E;
        okl &= fabsf(A2[n] - want) <= 1e-3f * (float)(n + 1) * L2E;
    }
    bool fast = __all_sync(0xffffffffu, okl);
    float Dd = (dir ? D_b : D_p)[v * DI + d];

    float h[16];
    #pragma unroll
    for (int n = 0; n < 16; n++) h[n] = 0.f;

    size_t rbase = ((size_t)c * 4 + b) * LQ;
    const float* xdb = g_xdbl + rbase * XD + 48 + lane;
    const float* dtp = g_dt   + rbase * DI + d;
    const f16*   uhp = g_uh   + rbase * DI + d;
    const f16*   ulp = g_ul   + rbase * DI + d;
    float* yp        = g_y    + rbase * DI + d;

    __shared__ __align__(16) float sBC[16][32];

    if (fast) {
        for (int chunk = 0; chunk < LQ / 16; chunk++) {
            __syncthreads();
            #pragma unroll
            for (int i = 0; i < 4; i++) {
                int sl = warp + i * 4;
                sBC[sl][lane] = xdb[(size_t)(chunk * 16 + sl) * XD];
            }
            float dtv[16], uhv[16], ulv[16];
            #pragma unroll
            for (int i = 0; i < 16; i++)
                dtv[i] = dtp[(size_t)(chunk * 16 + i) * DI];
            #pragma unroll
            for (int i = 0; i < 16; i++) {
                uhv[i] = __half2float(uhp[(size_t)(chunk * 16 + i) * DI]);
                ulv[i] = __half2float(ulp[(size_t)(chunk * 16 + i) * DI]);
            }
            __syncthreads();
            #pragma unroll
            for (int s16 = 0; s16 < 16; s16++) {
                int s = chunk * 16 + s16;
                float dt = dtv[s16];
                float u  = uhv[s16] + ulv[s16];
                float dtu = dt * u;
                float y0 = u * Dd, y1 = 0.f;
                float r;
                asm("ex2.approx.ftz.f32 %0, %1;" : "=f"(r) : "f"(dt * A2[0]));
                float rp[17];
                rp[1] = r;
                #pragma unroll
                for (int n = 2; n <= 16; n++) rp[n] = rp[n >> 1] * rp[n - (n >> 1)];
                #pragma unroll
                for (int n = 0; n < 16; n += 2) {
                    float b0 = sBC[s16][n],     c0 = sBC[s16][16 + n];
                    float b1 = sBC[s16][n + 1], c1 = sBC[s16][16 + n + 1];
                    h[n]     = fmaf(rp[n + 1], h[n],     dtu * b0);
                    h[n + 1] = fmaf(rp[n + 2], h[n + 1], dtu * b1);
                    y0 = fmaf(h[n],     c0, y0);
                    y1 = fmaf(h[n + 1], c1, y1);
                }
                yp[(size_t)s * DI] = y0 + y1;
            }
        }
    } else {
        for (int chunk = 0; chunk < LQ / 16; chunk++) {
            __syncthreads();
            #pragma unroll
            for (int i = 0; i < 4; i++) {
                int sl = warp + i * 4;
                sBC[sl][lane] = xdb[(size_t)(chunk * 16 + sl) * XD];
            }
            float dtv[16], uhv[16], ulv[16];
            #pragma unroll
            for (int i = 0; i < 16; i++)
                dtv[i] = dtp[(size_t)(chunk * 16 + i) * DI];
            #pragma unroll
            for (int i = 0; i < 16; i++) {
                uhv[i] = __half2float(uhp[(size_t)(chunk * 16 + i) * DI]);
                ulv[i] = __half2float(ulp[(size_t)(chunk * 16 + i) * DI]);
            }
            __syncthreads();
            #pragma unroll
            for (int s16 = 0; s16 < 16; s16++) {
                int s = chunk * 16 + s16;
                float dt = dtv[s16];
                float u  = uhv[s16] + ulv[s16];
                float dtu = dt * u;
                float y0 = u * Dd, y1 = 0.f;
                #pragma unroll
                for (int n = 0; n < 16; n += 2) {
                    float dA0, dA1;
                    asm("ex2.approx.ftz.f32 %0, %1;" : "=f"(dA0) : "f"(dt * A2[n]));
                    asm("ex2.approx.ftz.f32 %0, %1;" : "=f"(dA1) : "f"(dt * A2[n + 1]));
                    h[n]     = fmaf(dA0, h[n],     dtu * sBC[s16][n]);
                    h[n + 1] = fmaf(dA1, h[n + 1], dtu * sBC[s16][n + 1]);
                    y0 = fmaf(h[n],     sBC[s16][16 + n],     y0);
                    y1 = fmaf(h[n + 1], sBC[s16][16 + n + 1], y1);
                }
                yp[(size_t)s * DI] = y0 + y1;
            }
        }
    }
}

// ---------------- combine + gate, x4 vectorized ----------------
__global__ void combine_kernel()
{
    size_t idx4 = ((size_t)blockIdx.x * 256 + threadIdx.x) * 4;
    int d = (int)(idx4 % DI);
    size_t rm = idx4 / DI;
    int t = (int)(rm & (LQ - 1));
    int b = (int)((rm >> 10) & 3);
    int v = (int)(rm >> 12);
    float4 yf = *(const float4*)&g_y[(((size_t)(2 * v)     * 4 + b) * LQ + t)            * DI + d];
    float4 yb = *(const float4*)&g_y[(((size_t)(2 * v + 1) * 4 + b) * LQ + (LQ - 1 - t)) * DI + d];
    float4 z  = *(const float4*)&g_xz[((size_t)v * MROWS + b * LQ + t) * (2 * DI) + DI + d];
    float v0 = (yf.x + yb.x) * (z.x / (1.f + __expf(-z.x)));
    float v1 = (yf.y + yb.y) * (z.y / (1.f + __expf(-z.y)));
    float v2 = (yf.z + yb.z) * (z.z / (1.f + __expf(-z.z)));
    float v3 = (yf.w + yb.w) * (z.w / (1.f + __expf(-z.w)));
    f16 h0, l0, h1, l1, h2, l2, h3, l3;
    split1(v0, h0, l0); split1(v1, h1, l1);
    split1(v2, h2, l2); split1(v3, h3, l3);
    *(uint2*)(g_ych + idx4) = make_uint2(packh(h0, h1), packh(h2, h3));
    *(uint2*)(g_ycl + idx4) = make_uint2(packh(l0, l1), packh(l2, l3));
}

// ---------------- launch ----------------
extern "C" void kernel_launch(void* const* d_in, const int* in_sizes, int n_in,
                              void* d_out, int out_size)
{
    const float* h_r        = (const float*)d_in[0];
    const float* h_i        = (const float*)d_in[1];
    const float* ln_w       = (const float*)d_in[2];
    const float* ln_b       = (const float*)d_in[3];
    const float* in_w       = (const float*)d_in[4];
    const float* conv_w     = (const float*)d_in[5];
    const float* conv_bias  = (const float*)d_in[6];
    const float* xp_w       = (const float*)d_in[7];
    const float* dtp_w      = (const float*)d_in[8];
    const float* dtp_bias   = (const float*)d_in[9];
    const float* A_log      = (const float*)d_in[10];
    const float* D_p        = (const float*)d_in[11];
    const float* conv_w_b   = (const float*)d_in[12];
    const float* conv_bias_b= (const float*)d_in[13];
    const float* xp_w_b     = (const float*)d_in[14];
    const float* dtp_w_b    = (const float*)d_in[15];
    const float* dtp_bias_b = (const float*)d_in[16];
    const float* A_b_log    = (const float*)d_in[17];
    const float* D_b        = (const float*)d_in[18];
    const float* out_w      = (const float*)d_in[19];
    float* out = (float*)d_out;

    f16 *p_hnh, *p_hnl, *p_uh, *p_ul, *p_xdh, *p_xdl, *p_ych, *p_ycl;
    f16 *p_inwh, *p_inwl, *p_xpwh, *p_xpwl, *p_xpwhb, *p_xpwlb;
    f16 *p_dtwh, *p_dtwl, *p_dtwhb, *p_dtwlb, *p_outwh, *p_outwl;
    float *p_xz, *p_xdbl, *p_dt;
    cudaGetSymbolAddress((void**)&p_hnh, g_hnh);   cudaGetSymbolAddress((void**)&p_hnl, g_hnl);
    cudaGetSymbolAddress((void**)&p_uh,  g_uh);    cudaGetSymbolAddress((void**)&p_ul,  g_ul);
    cudaGetSymbolAddress((void**)&p_xdh, g_xdblh); cudaGetSymbolAddress((void**)&p_xdl, g_xdbll);
    cudaGetSymbolAddress((void**)&p_ych, g_ych);   cudaGetSymbolAddress((void**)&p_ycl, g_ycl);
    cudaGetSymbolAddress((void**)&p_inwh, g_inwh); cudaGetSymbolAddress((void**)&p_inwl, g_inwl);
    cudaGetSymbolAddress((void**)&p_xpwh, g_xpwh); cudaGetSymbolAddress((void**)&p_xpwl, g_xpwl);
    cudaGetSymbolAddress((void**)&p_xpwhb, g_xpwhb); cudaGetSymbolAddress((void**)&p_xpwlb, g_xpwlb);
    cudaGetSymbolAddress((void**)&p_dtwh, g_dtwh); cudaGetSymbolAddress((void**)&p_dtwl, g_dtwl);
    cudaGetSymbolAddress((void**)&p_dtwhb, g_dtwhb); cudaGetSymbolAddress((void**)&p_dtwlb, g_dtwlb);
    cudaGetSymbolAddress((void**)&p_outwh, g_outwh); cudaGetSymbolAddress((void**)&p_outwl, g_outwl);
    cudaGetSymbolAddress((void**)&p_xz, g_xz);
    cudaGetSymbolAddress((void**)&p_xdbl, g_xdbl);
    cudaGetSymbolAddress((void**)&p_dt, g_dt);

    static int s_attr = 0;
    if (!s_attr) {
        cudaFuncSetAttribute(gemm_mma2<false>, cudaFuncAttributeMaxDynamicSharedMemorySize, GSM);
        cudaFuncSetAttribute(gemm_mma2<true>,  cudaFuncAttributeMaxDynamicSharedMemorySize, GSM);
        s_attr = 1;
    }

    // idx 0: in_proj weight split
    split_inw<<<(S_INW + 255) / 256, 256>>>(in_w);

    // idx 1: LayerNorm
    ln_kernel<<<2 * MROWS, 192>>>(h_r, h_i, ln_w, ln_b);

    // idx 2: remaining weight splits
    split_rest<<<(S_REST + 255) / 256, 256>>>(xp_w, xp_w_b, dtp_w, dtp_w_b, out_w);

    // idx 3 (profiled): in_proj x-half (N cols 0..1535, 3-pass)
    gemm_mma2<false><<<dim3(24, 32, 2), 256, GSM>>>(
        p_hnh, p_hnl, p_inwh, p_inwl, nullptr, nullptr,
        p_xz, DI, 768, 768, 768, 3072,
        (size_t)MROWS * DM, (size_t)3072 * DM, (size_t)MROWS * 3072,
        nullptr, nullptr, 0, 0, 0);

    // idx 4: in_proj z-half (N cols 1536..3071, 2-pass; W rows +1536, C cols +1536)
    gemm_mma2<true><<<dim3(24, 32, 2), 256, GSM>>>(
        p_hnh, p_hnl, p_inwh + (size_t)DI * DM, p_inwl + (size_t)DI * DM, nullptr, nullptr,
        p_xz + DI, DI, 768, 768, 768, 3072,
        (size_t)MROWS * DM, (size_t)3072 * DM, (size_t)MROWS * 3072,
        nullptr, nullptr, 0, 0, 0);

    // idx 5: conv + silu -> uh/ul
    conv_silu_kernel<<<dim3(3, 16, 16), 128>>>(conv_w, conv_bias, conv_w_b, conv_bias_b);

    // idx 6: xp projection (N=80, K=1536); 3-pass (feeds dt/B/C)
    gemm_mma2<false><<<dim3(2, 32, 4), 256, GSM>>>(
        p_uh, p_ul, p_xpwh, p_xpwl, p_xpwhb, p_xpwlb,
        p_xdbl, XD, DI, DI, DI, XD,
        (size_t)MROWS * DI, (size_t)XD * DI, (size_t)MROWS * XD,
        nullptr, nullptr, 0, 2, 1);

    // idx 7: dt projection + softplus (N=1536, K=64 padded); 3-pass
    gemm_mma2<false><<<dim3(24, 32, 4), 256, GSM>>>(
        p_xdh, p_xdl, p_dtwh, p_dtwl, p_dtwhb, p_dtwlb,
        p_dt, DI, 64, 64, 64, DI,
        (size_t)MROWS * 64, (size_t)DI * 64, (size_t)MROWS * DI,
        dtp_bias, dtp_bias_b, DI, 1, 1);

    // idx 8: selective scan
    scan_kernel<<<192, 128>>>(A_log, A_b_log, D_p, D_b);

    // idx 9: combine + gate
    combine_kernel<<<(2 * MROWS * DI) / 1024, 256>>>();

    // idx 10: out_proj (M=4096, N=768, K=1536); 2-pass (final op)
    gemm_mma2<true><<<dim3(12, 32, 2), 256, GSM>>>(
        p_ych, p_ycl, p_outwh, p_outwl, nullptr, nullptr,
        out, DM, DI, DI, DI, DM,
        (size_t)MROWS * DI, (size_t)DM * DI, (size_t)MROWS * DM,
        nullptr, nullptr, 0, 0, 0);
}